// round 8
// baseline (speedup 1.0000x reference)
#include <cuda_runtime.h>
#include <cuda_bf16.h>

// EmbeddedGCN: out[b,i,o] = relu( sum_j adj[b,i,j] * (concat(s1,s2)[b,i,j,:] @ W)[o] + bias[o] )
// Linearity rewrite:
//   y[b,i,f]   = sum_j adj[b,i,j] * concat(s1,s2)[b,i,j,f]     (gated gather-reduce)
//   out[b,i,o] = relu( sum_f y[f]*W[f,o] + bias[o]*rowsum(adj) )
//
// B=16, M=128, FE=64 (concat 128), FO=128.
// Block = 1024 threads (32 warps), RPB=8 rows, FOUR warps per row, grid 256.
// Each warp issues a single MLP-8 batch covering its 8 of the ~32 compacted
// neighbors -> the per-row dependent-DRAM-round chain collapses from 4 to ~1.
// Phase 2: 1024 threads = 8 rows x 128 outputs, one output per thread.

#define BM 128
#define FE 64
#define FT 128
#define FO 128
#define RPB 8
#define NW 32

__global__ __launch_bounds__(1024, 1)
void gcn_fused4(const float* __restrict__ s1,
                const float* __restrict__ s2,
                const float* __restrict__ adj,
                const float* __restrict__ W,
                const float* __restrict__ bias,
                float* __restrict__ out)
{
    __shared__ int   jidx_s[RPB][BM];
    __shared__ float aval_s[RPB][BM];
    __shared__ float part_s[NW][FT];     // 16 KB
    __shared__ float y_s[RPB][FT];
    __shared__ float rowsum_s[RPB];

    const int tid  = threadIdx.x;        // 0..1023
    const int lane = tid & 31;
    const int w    = tid >> 5;           // 0..31
    const int r    = w >> 2;             // local row 0..7
    const int sub  = w & 3;              // which quarter of the neighbor list
    const int bi0  = blockIdx.x * RPB;
    const int row  = bi0 + r;            // flat b*M + i

    // ---- Phase 1a: adjacency load + warp-prefix compaction ----
    // All 4 warps of a row do identical compaction (duplicate identical writes,
    // race-free) so each warp can proceed to its gather without a block barrier.
    const float4 av = *(const float4*)(adj + (size_t)row * BM + lane * 4);
    int   cnt  = 0;
    float rsum = 0.0f;
    {
        const unsigned lt = (1u << lane) - 1u;
        #pragma unroll
        for (int q = 0; q < 4; q++) {
            const float a = (q == 0) ? av.x : (q == 1) ? av.y : (q == 2) ? av.z : av.w;
            const unsigned m = __ballot_sync(0xFFFFFFFFu, a != 0.0f);
            if (a != 0.0f) {
                const int pos = cnt + __popc(m & lt);
                jidx_s[r][pos] = lane * 4 + q;
                aval_s[r][pos] = a;
            }
            cnt  += __popc(m);
            rsum += a;
        }
        #pragma unroll
        for (int off = 16; off > 0; off >>= 1)
            rsum += __shfl_xor_sync(0xFFFFFFFFu, rsum, off);
        if (sub == 0 && lane == 0) rowsum_s[r] = rsum;
    }
    __syncwarp();

    // ---- Phase 1b: gather-reduce, one predicated MLP-8 batch per 32 neighbors ----
    // lane -> one float4 of the 128-wide concat row:
    //   lanes 0..15  -> s1, float4 idx = lane        (features 0..63)
    //   lanes 16..31 -> s2, float4 idx = lane - 16   (features 64..127)
    const float4* base4;
    {
        const size_t row0 = (size_t)row * (size_t)(BM * FE);
        base4 = (lane < 16) ? ((const float4*)(s1 + row0) + lane)
                            : ((const float4*)(s2 + row0) + (lane - 16));
    }

    float4 acc = make_float4(0.f, 0.f, 0.f, 0.f);
    for (int k0 = sub * 8; k0 < cnt; k0 += 32) {
        const int kend = min(k0 + 8, cnt);
        const int jsafe = jidx_s[r][k0];
        int   j[8];
        float a[8];
        #pragma unroll
        for (int t = 0; t < 8; t++) {
            const int  kk = k0 + t;
            const bool v  = kk < kend;
            j[t] = v ? jidx_s[r][kk] : jsafe;   // dummy -> L1 hit
            a[t] = v ? aval_s[r][kk] : 0.0f;    // contributes 0
        }
        float4 vv[8];
        #pragma unroll
        for (int t = 0; t < 8; t++) vv[t] = __ldg(base4 + (size_t)j[t] * 16);
        #pragma unroll
        for (int t = 0; t < 8; t++) {
            acc.x = fmaf(a[t], vv[t].x, acc.x);
            acc.y = fmaf(a[t], vv[t].y, acc.y);
            acc.z = fmaf(a[t], vv[t].z, acc.z);
            acc.w = fmaf(a[t], vv[t].w, acc.w);
        }
    }

    {
        const int fb = (lane < 16) ? (lane * 4) : (FE + (lane - 16) * 4);
        *(float4*)&part_s[w][fb] = acc;
    }
    __syncthreads();

    // ---- Combine 4 partials per row: 1024 threads = 8 rows x 128 features ----
    {
        const int rr = tid >> 7;
        const int ff = tid & (FT - 1);
        y_s[rr][ff] = part_s[4 * rr + 0][ff] + part_s[4 * rr + 1][ff]
                    + part_s[4 * rr + 2][ff] + part_s[4 * rr + 3][ff];
    }
    __syncthreads();

    // ---- Phase 2: one output per thread ----
    const int ro = tid >> 7;             // local row 0..7
    const int o  = tid & (FO - 1);

    float accO = __ldg(bias + o) * rowsum_s[ro];
    #pragma unroll 8
    for (int f = 0; f < FT; f += 4) {
        const float4 y  = *(const float4*)&y_s[ro][f];
        const float  w0 = __ldg(W + (f + 0) * FO + o);
        const float  w1 = __ldg(W + (f + 1) * FO + o);
        const float  w2 = __ldg(W + (f + 2) * FO + o);
        const float  w3 = __ldg(W + (f + 3) * FO + o);
        accO = fmaf(y.x, w0, accO);
        accO = fmaf(y.y, w1, accO);
        accO = fmaf(y.z, w2, accO);
        accO = fmaf(y.w, w3, accO);
    }

    out[(size_t)(bi0 + ro) * FO + o] = fmaxf(accO, 0.0f);
}

extern "C" void kernel_launch(void* const* d_in, const int* in_sizes, int n_in,
                              void* d_out, int out_size)
{
    const float* s1   = (const float*)d_in[0];  // (16,128,128,64)
    const float* s2   = (const float*)d_in[1];  // (16,128,128,64)
    const float* adj  = (const float*)d_in[2];  // (16,128,128)
    const float* W    = (const float*)d_in[3];  // (128,128)
    const float* bias = (const float*)d_in[4];  // (128,)
    float* out = (float*)d_out;                 // (16,128,128)

    gcn_fused4<<<(16 * 128) / RPB, 1024>>>(s1, s2, adj, W, bias, out);
}